// round 16
// baseline (speedup 1.0000x reference)
#include <cuda_runtime.h>
#include <math_constants.h>

// Problem shape (fixed by reference): B=32, C=8, H=W=256
#define HM        256        // B*C heatmaps
#define HW        65536      // H*W elements per heatmap
#define NBLK      (2 * HM)   // 512 blocks, ONE wave: 256 input + 256 target
#define T1        512        // threads per block
#define NIT       (HW / 4 / T1)   // 32 float4 iterations per thread

// Scratch (no device allocation allowed -> __device__ globals, zero-initialized)
__device__ float        g_s [HM];      // softmax sum         (input blocks)
__device__ float        g_sx[HM];      // x expectation sum
__device__ float        g_sy[HM];      // y expectation sum
__device__ float        g_bv[HM];      // target max          (target blocks)
__device__ int          g_bi[HM];      // target argmax index
__device__ float        g_m [HM];      // per-heatmap MSE
__device__ unsigned int g_hmc[HM];     // per-heatmap pair tickets (to 2)
__device__ unsigned int g_count;       // heatmaps-done ticket (to HM)

// Stream-specialized single-wave kernel: each block streams ONE contiguous
// 256KB region of ONE tensor (max per-block DRAM row locality, single
// request stream per block). Input block b computes softmax sums for heatmap
// b; target block b+256 computes the argmax for heatmap b. The 2nd finisher
// of each pair folds the heatmap's MSE; the last heatmap-finisher sums /B.
__global__ __launch_bounds__(T1)
void dsnt_fused(const float* __restrict__ inp, const float* __restrict__ tgt,
                float* __restrict__ out) {
    const int  blk    = blockIdx.x;
    const bool is_inp = blk < HM;
    const int  hm     = is_inp ? blk : blk - HM;

    const int tid = threadIdx.x;
    const int wid = tid >> 5, lid = tid & 31;

    __shared__ float sh_a[T1 / 32];
    __shared__ float sh_b[T1 / 32];
    __shared__ float sh_c[T1 / 32];
    __shared__ int   sh_i[T1 / 32];
    __shared__ unsigned int sh_ticket;

    if (is_inp) {
        // ================= input block: s, sx, sy =================
        const float4* __restrict__ in4 =
            (const float4*)(inp + (size_t)hm * HW);
        // w = (4*tid)&255 per-thread constant; h advances 8 rows / iter
        const float x0    = (float)(((4 * tid) & 255) - 127) * (1.0f / 256.0f);
        const float ybase = (float)((tid >> 6) - 127) * (1.0f / 256.0f);

        float s = 0.f, sx = 0.f, sy = 0.f;
        #pragma unroll 8
        for (int it = 0; it < NIT; ++it) {
            const float4 v = in4[tid + it * T1];
            const float  y = ybase + (float)it * 0.03125f;
            const float e0 = __expf(v.x);
            const float e1 = __expf(v.y);
            const float e2 = __expf(v.z);
            const float e3 = __expf(v.w);
            const float es = (e0 + e1) + (e2 + e3);
            s += es;
            sy = fmaf(y, es, sy);
            // sum e_k * x_{w+k} = x0*es + (e1 + 2e2 + 3e3)/256
            sx = fmaf(x0, es,
                 fmaf(1.0f / 256.0f, fmaf(3.f, e3, fmaf(2.f, e2, e1)), sx));
        }

        #pragma unroll
        for (int o = 16; o > 0; o >>= 1) {
            s  += __shfl_down_sync(0xffffffffu, s,  o);
            sx += __shfl_down_sync(0xffffffffu, sx, o);
            sy += __shfl_down_sync(0xffffffffu, sy, o);
        }
        if (lid == 0) { sh_a[wid] = s; sh_b[wid] = sx; sh_c[wid] = sy; }
        __syncthreads();
        if (wid == 0) {
            const bool ok = lid < (T1 / 32);
            s  = ok ? sh_a[lid] : 0.f;
            sx = ok ? sh_b[lid] : 0.f;
            sy = ok ? sh_c[lid] : 0.f;
            #pragma unroll
            for (int o = 8; o > 0; o >>= 1) {
                s  += __shfl_down_sync(0xffffffffu, s,  o);
                sx += __shfl_down_sync(0xffffffffu, sx, o);
                sy += __shfl_down_sync(0xffffffffu, sy, o);
            }
            if (lid == 0) {
                g_s [hm] = s;
                g_sx[hm] = sx;
                g_sy[hm] = sy;
            }
        }
    } else {
        // ================= target block: argmax =================
        const float4* __restrict__ tg4 =
            (const float4*)(tgt + (size_t)hm * HW);
        float bv = -CUDART_INF_F;
        int   bi = 0x7fffffff;
        #pragma unroll 8
        for (int it = 0; it < NIT; ++it) {
            const float4 t = tg4[tid + it * T1];
            // FIRST-index tie-break: fmax tree + rare branch
            const float qmax = fmaxf(fmaxf(t.x, t.y), fmaxf(t.z, t.w));
            if (qmax > bv) {
                const int off = it * (4 * T1) + 4 * tid;
                bv = qmax;
                bi = (t.x == qmax) ? off :
                     (t.y == qmax) ? off + 1 :
                     (t.z == qmax) ? off + 2 : off + 3;
            }
        }

        #pragma unroll
        for (int o = 16; o > 0; o >>= 1) {
            const float ov = __shfl_down_sync(0xffffffffu, bv, o);
            const int   oi = __shfl_down_sync(0xffffffffu, bi, o);
            if (ov > bv || (ov == bv && oi < bi)) { bv = ov; bi = oi; }
        }
        if (lid == 0) { sh_a[wid] = bv; sh_i[wid] = bi; }
        __syncthreads();
        if (wid == 0) {
            const bool ok = lid < (T1 / 32);
            bv = ok ? sh_a[lid] : -CUDART_INF_F;
            bi = ok ? sh_i[lid] : 0x7fffffff;
            #pragma unroll
            for (int o = 8; o > 0; o >>= 1) {
                const float ov = __shfl_down_sync(0xffffffffu, bv, o);
                const int   oi = __shfl_down_sync(0xffffffffu, bi, o);
                if (ov > bv || (ov == bv && oi < bi)) { bv = ov; bi = oi; }
            }
            if (lid == 0) {
                g_bv[hm] = bv;
                g_bi[hm] = bi;
            }
        }
    }

    // ---- pair ticket: 2nd finisher of (input, target) folds the MSE ----
    if (tid == 0) {
        __threadfence();                              // release my partials
        unsigned int tk = 0xffffffffu;
        if (atomicAdd(&g_hmc[hm], 1u) == 1u) {
            __threadfence();                          // acquire peer partials
            const float fs  = __ldcg(&g_s [hm]);
            const float fsx = __ldcg(&g_sx[hm]);
            const float fsy = __ldcg(&g_sy[hm]);
            const int   fbi = __ldcg(&g_bi[hm]);
            const float inv = 1.0f / fs;
            const float px = fsx * inv;
            const float py = fsy * inv;
            const float tx = (float)((fbi & 255) - 127) * (1.0f / 256.0f);
            const float ty = (float)((fbi >> 8)  - 127) * (1.0f / 256.0f);
            const float dx = px - tx;
            const float dy = py - ty;
            g_m[hm] = 0.5f * (dx * dx + dy * dy);
            __threadfence();                          // release g_m
            tk = atomicAdd(&g_count, 1u);
        }
        sh_ticket = tk;
    }
    __syncthreads();
    if (sh_ticket != HM - 1) return;     // not the last heatmap-finisher

    // ---- final epilogue: fixed-order sum of 256 heatmap MSEs / B ----
    float m = 0.f;
    if (tid < HM) {
        __threadfence();                 // acquire g_m (8 warps only)
        m = __ldcg(&g_m[tid]);
        g_hmc[tid] = 0;                  // reset pair tickets for next replay
    }
    #pragma unroll
    for (int o = 16; o > 0; o >>= 1)
        m += __shfl_down_sync(0xffffffffu, m, o);
    __shared__ float sh_m[T1 / 32];
    if (lid == 0) sh_m[wid] = m;
    __syncthreads();
    if (tid == 0) {
        float tot = 0.f;
        #pragma unroll
        for (int w = 0; w < 8; ++w) tot += sh_m[w];   // warps 0..7 hold tids<256
        out[0] = tot * (1.0f / 32.0f);                // divide by B
        g_count = 0;                                   // reset for next replay
    }
}

extern "C" void kernel_launch(void* const* d_in, const int* in_sizes, int n_in,
                              void* d_out, int out_size) {
    const float* inp = (const float*)d_in[0];
    const float* tgt = (const float*)d_in[1];
    float* out = (float*)d_out;
    (void)in_sizes; (void)n_in; (void)out_size;

    dsnt_fused<<<NBLK, T1>>>(inp, tgt, out);
}

// round 17
// speedup vs baseline: 1.0011x; 1.0011x over previous
#include <cuda_runtime.h>
#include <math_constants.h>

// Problem shape (fixed by reference): B=32, C=8, H=W=256
#define HM        256        // B*C heatmaps
#define HW        65536      // H*W elements per heatmap
#define SLICES    2          // blocks per heatmap
#define NBLK      (HM * SLICES)          // 512 blocks -> ONE wave (4/SM x 148)
#define SLICE_EL  (HW / SLICES)          // 32768 elements per slice
#define T1        512                    // threads per block
#define V4_PER_T  (SLICE_EL / 4 / T1)    // 16 float4 quads / thread / tensor

// Scratch (no device allocation allowed -> __device__ globals, zero-initialized)
__device__ float        g_s [NBLK];
__device__ float        g_sx[NBLK];
__device__ float        g_sy[NBLK];
__device__ float        g_bv[NBLK];
__device__ int          g_bi[NBLK];
__device__ float        g_m [HM];      // per-heatmap MSE (distributed fold)
__device__ unsigned int g_hmc[HM];     // per-heatmap pair tickets
__device__ unsigned int g_count;       // heatmaps-done ticket

// Best-measured configuration (R14: dur 29.09us) + partial unroll(8) so the
// hot-loop body fits the 6KB L0 I-cache (full 16x unroll is ~7.7KB; R16's
// unroll-8 variant posted the equal-best kernel time at identical BW).
//  - single wave: 512 blocks x 512 threads, 32 regs -> 4 blocks/SM resident
//  - hoisted coords: x-weight per-thread constant, y advances 8 rows/iter
//  - distributed fold: 2nd finisher of each heatmap folds its 2 slices;
//    the 256th heatmap-finisher does the fixed-order 256-float sum / B.
__global__ __launch_bounds__(T1)
void dsnt_fused(const float* __restrict__ inp, const float* __restrict__ tgt,
                float* __restrict__ out) {
    const int blk = blockIdx.x;
    const int hm  = blk >> 1;       // heatmap id
    const int sl  = blk & 1;        // slice id
    const size_t base = (size_t)hm * HW + (size_t)sl * SLICE_EL;
    const float4* __restrict__ in4 = (const float4*)(inp + base);
    const float4* __restrict__ tg4 = (const float4*)(tgt + base);

    const int tid  = threadIdx.x;
    const int off0 = sl * SLICE_EL;          // element offset within heatmap
    const int eoff = off0 + 4 * tid;         // this thread's first element idx

    // hoisted coordinates: w = (4*tid)&255 is per-thread constant;
    // h advances by 8 per iteration (stride 2048 elements = 8 rows).
    const float x0    = (float)(((4 * tid) & 255) - 127) * (1.0f / 256.0f);
    const float ybase = (float)((eoff >> 8) - 127) * (1.0f / 256.0f);

    float s = 0.f, sx = 0.f, sy = 0.f;
    float bv = -CUDART_INF_F;
    int   bi = 0x7fffffff;

    #pragma unroll 8
    for (int it = 0; it < V4_PER_T; ++it) {
        const float4 v = in4[tid + it * T1];
        const float4 t = tg4[tid + it * T1];
        const float  y = ybase + (float)it * 0.03125f;   // +8 rows / iter

        const float e0 = __expf(v.x);
        const float e1 = __expf(v.y);
        const float e2 = __expf(v.z);
        const float e3 = __expf(v.w);
        const float es = (e0 + e1) + (e2 + e3);
        s += es;
        sy = fmaf(y, es, sy);
        // sum e_k * x_{w+k} = x0*es + (e1 + 2e2 + 3e3)/256
        sx = fmaf(x0, es,
             fmaf(1.0f / 256.0f, fmaf(3.f, e3, fmaf(2.f, e2, e1)), sx));

        // target argmax with FIRST-index tie-break (rare branch)
        const float qmax = fmaxf(fmaxf(t.x, t.y), fmaxf(t.z, t.w));
        if (qmax > bv) {
            const int off = eoff + it * 2048;
            bv = qmax;
            bi = (t.x == qmax) ? off :
                 (t.y == qmax) ? off + 1 :
                 (t.z == qmax) ? off + 2 : off + 3;
        }
    }

    // warp reduction
    #pragma unroll
    for (int o = 16; o > 0; o >>= 1) {
        s  += __shfl_down_sync(0xffffffffu, s,  o);
        sx += __shfl_down_sync(0xffffffffu, sx, o);
        sy += __shfl_down_sync(0xffffffffu, sy, o);
        const float ov = __shfl_down_sync(0xffffffffu, bv, o);
        const int   oi = __shfl_down_sync(0xffffffffu, bi, o);
        if (ov > bv || (ov == bv && oi < bi)) { bv = ov; bi = oi; }
    }

    __shared__ float sh_s [T1 / 32];
    __shared__ float sh_sx[T1 / 32];
    __shared__ float sh_sy[T1 / 32];
    __shared__ float sh_bv[T1 / 32];
    __shared__ int   sh_bi[T1 / 32];
    __shared__ unsigned int sh_ticket;
    const int wid = tid >> 5, lid = tid & 31;
    if (lid == 0) {
        sh_s[wid] = s; sh_sx[wid] = sx; sh_sy[wid] = sy;
        sh_bv[wid] = bv; sh_bi[wid] = bi;
    }
    __syncthreads();

    if (wid == 0) {
        const bool ok = lid < (T1 / 32);
        s  = ok ? sh_s [lid] : 0.f;
        sx = ok ? sh_sx[lid] : 0.f;
        sy = ok ? sh_sy[lid] : 0.f;
        bv = ok ? sh_bv[lid] : -CUDART_INF_F;
        bi = ok ? sh_bi[lid] : 0x7fffffff;
        #pragma unroll
        for (int o = 8; o > 0; o >>= 1) {
            s  += __shfl_down_sync(0xffffffffu, s,  o);
            sx += __shfl_down_sync(0xffffffffu, sx, o);
            sy += __shfl_down_sync(0xffffffffu, sy, o);
            const float ov = __shfl_down_sync(0xffffffffu, bv, o);
            const int   oi = __shfl_down_sync(0xffffffffu, bi, o);
            if (ov > bv || (ov == bv && oi < bi)) { bv = ov; bi = oi; }
        }
        if (lid == 0) {
            // store this slice's partials, release, take the heatmap ticket
            g_s [blk] = s;
            g_sx[blk] = sx;
            g_sy[blk] = sy;
            g_bv[blk] = bv;
            g_bi[blk] = bi;
            __threadfence();                              // release partials
            unsigned int tk = 0xffffffffu;
            if (atomicAdd(&g_hmc[hm], 1u) == 1u) {
                // 2nd slice of this heatmap done -> fold NOW (overlapped
                // with other blocks still streaming)
                __threadfence();                          // acquire partials
                float fs = 0.f, fsx = 0.f, fsy = 0.f;
                float fbv = -CUDART_INF_F;
                int   fbi = 0x7fffffff;
                #pragma unroll
                for (int k = 0; k < SLICES; ++k) {        // fixed order
                    const int idx = hm * SLICES + k;
                    fs  += __ldcg(&g_s [idx]);
                    fsx += __ldcg(&g_sx[idx]);
                    fsy += __ldcg(&g_sy[idx]);
                    const float v = __ldcg(&g_bv[idx]);
                    const int   i = __ldcg(&g_bi[idx]);
                    if (v > fbv || (v == fbv && i < fbi)) { fbv = v; fbi = i; }
                }
                const float inv = 1.0f / fs;
                const float px = fsx * inv;
                const float py = fsy * inv;
                const float tx = (float)((fbi & 255) - 127) * (1.0f / 256.0f);
                const float ty = (float)((fbi >> 8)  - 127) * (1.0f / 256.0f);
                const float dx = px - tx;
                const float dy = py - ty;
                g_m[hm] = 0.5f * (dx * dx + dy * dy);
                __threadfence();                          // release g_m
                tk = atomicAdd(&g_count, 1u);
            }
            sh_ticket = tk;
        }
    }
    __syncthreads();
    if (sh_ticket != HM - 1) return;     // not the last heatmap-finisher

    // ---- final epilogue: fixed-order sum of 256 heatmap MSEs / B ----
    float m = 0.f;
    if (tid < HM) {
        __threadfence();                 // acquire g_m (8 warps only)
        m = __ldcg(&g_m[tid]);
        g_hmc[tid] = 0;                  // reset pair tickets for next replay
    }
    #pragma unroll
    for (int o = 16; o > 0; o >>= 1)
        m += __shfl_down_sync(0xffffffffu, m, o);
    __shared__ float sh_m[T1 / 32];
    if (lid == 0) sh_m[wid] = m;
    __syncthreads();
    if (tid == 0) {
        float tot = 0.f;
        #pragma unroll
        for (int w = 0; w < 8; ++w) tot += sh_m[w];   // warps 0..7 hold tids<256
        out[0] = tot * (1.0f / 32.0f);                // divide by B
        g_count = 0;                                   // reset for next replay
    }
}

extern "C" void kernel_launch(void* const* d_in, const int* in_sizes, int n_in,
                              void* d_out, int out_size) {
    const float* inp = (const float*)d_in[0];
    const float* tgt = (const float*)d_in[1];
    float* out = (float*)d_out;
    (void)in_sizes; (void)n_in; (void)out_size;

    dsnt_fused<<<NBLK, T1>>>(inp, tgt, out);
}